// round 15
// baseline (speedup 1.0000x reference)
#include <cuda_runtime.h>
#include <cuda_fp16.h>
#include <cuda_bf16.h>
#include <math.h>

#define N_NODES 50000
#define NODE_DIM 64
#define DEPTH 2
#define FEAT 192           // 64*(DEPTH+1)
#define E_EDGES 1200000
#define R_REL 500
#define DEG 24

// ---------------- scratch (device globals: allocation-free) ----------------
__device__ float    g_attW[DEPTH * R_REL];      // per-relation attention logit per layer
__device__ __half   g_nrelh[R_REL * NODE_DIM];  // l2-normalized rel_emb (fp16)
__device__ __half   g_fh0[N_NODES * NODE_DIM];  // tanh(features) fp16
__device__ __half   g_fh1[N_NODES * NODE_DIM];  // layer-0 output fp16
// fp16 MMA B-fragment tables: uint2 per (k16-step, col, t): (b0,b1) halves
__device__ uint2 g_npTH[12 * 64 * 4];           // normalized proxy^T  (k=192, n=64)
__device__ uint2 g_prxH[4 * 192 * 4];           // proxy [k][n]        (k=64,  n=192)
__device__ uint2 g_WtH[12 * 192 * 4];           // gate_w^T [k][c]     (k=192, n=192)

__device__ __forceinline__ unsigned h2bits(__half2 h) {
    union { __half2 h; unsigned u; } c; c.h = h; return c.u;
}
__device__ __forceinline__ __half2 bits2h(unsigned u) {
    union { unsigned u; __half2 h; } c; c.u = u; return c.h;
}
__device__ __forceinline__ float2 unpk(unsigned u) { return __half22float2(bits2h(u)); }
__device__ __forceinline__ unsigned pack2h(float a, float b) {
    return h2bits(__float22half2_rn(make_float2(a, b)));
}
// half index inside the uint2-pair B table for element (k, c)
__device__ __forceinline__ int packslotH(int k, int c, int ncols) {
    return ((((k >> 4) * ncols + c) * 4 + ((k >> 1) & 3)) * 4)
         + (((k >> 3) & 1) * 2) + (k & 1);
}

// ---------------- fused setup: tanh + fp16 table packing + rel normalize ---
#define TB_TANH ((N_NODES * 16 + 255) / 256)
#define TB_TABS ((FEAT * FEAT + 64 * FEAT + 255) / 256)
#define TB_PREP ((564 * 32 + 255) / 256)
__global__ void setup_kernel(const float* __restrict__ features,
                             float* __restrict__ out,
                             const float* __restrict__ rel_emb,
                             const float* __restrict__ attn_kernels,
                             const float* __restrict__ proxy,
                             const float* __restrict__ gw) {
    int b = blockIdx.x;
    if (b < TB_TANH) {
        int idx = b * blockDim.x + threadIdx.x;
        if (idx >= N_NODES * 16) return;
        int i = idx >> 4;
        int j4 = (idx & 15) << 2;
        float4 v = *(const float4*)(features + i * NODE_DIM + j4);
        float4 tv = make_float4(tanhf(v.x), tanhf(v.y), tanhf(v.z), tanhf(v.w));
        *(float4*)(out + (long)i * FEAT + j4) = tv;
        *(uint2*)(g_fh0 + i * NODE_DIM + j4) =
            make_uint2(pack2h(tv.x, tv.y), pack2h(tv.z, tv.w));
        return;
    }
    if (b < TB_TANH + TB_TABS) {
        int idx = (b - TB_TANH) * blockDim.x + threadIdx.x;
        if (idx < FEAT * FEAT) {
            int k = idx / FEAT, c = idx - k * FEAT;
            ((__half*)g_WtH)[packslotH(k, c, FEAT)] = __float2half_rn(gw[c * FEAT + k]);
        } else if (idx < FEAT * FEAT + 64 * FEAT) {
            int j = idx - FEAT * FEAT;
            int k = j / FEAT, c = j - k * FEAT;
            ((__half*)g_prxH)[packslotH(k, c, FEAT)] = __float2half_rn(proxy[k * FEAT + c]);
        }
        return;
    }
    int w = ((b - TB_TANH - TB_TABS) * blockDim.x + threadIdx.x) >> 5;
    int lane = threadIdx.x & 31;
    if (w < R_REL) {
        float2 v = ((const float2*)(rel_emb + w * NODE_DIM))[lane];
        float ss = v.x * v.x + v.y * v.y;
        #pragma unroll
        for (int o = 16; o; o >>= 1) ss += __shfl_xor_sync(0xffffffffu, ss, o);
        float inv = 1.0f / fmaxf(sqrtf(ss), 1e-12f);
        float2 nv = make_float2(v.x * inv, v.y * inv);
        ((__half2*)(g_nrelh + w * NODE_DIM))[lane] = __float22half2_rn(nv);
        float2 a0 = ((const float2*)attn_kernels)[lane];
        float2 a1 = ((const float2*)(attn_kernels + NODE_DIM))[lane];
        float d0 = nv.x * a0.x + nv.y * a0.y;
        float d1 = nv.x * a1.x + nv.y * a1.y;
        #pragma unroll
        for (int o = 16; o; o >>= 1) {
            d0 += __shfl_xor_sync(0xffffffffu, d0, o);
            d1 += __shfl_xor_sync(0xffffffffu, d1, o);
        }
        if (lane == 0) { g_attW[w] = d0; g_attW[R_REL + w] = d1; }
    } else if (w < R_REL + 64) {
        int j = w - R_REL;
        float v[6];
        float ss = 0.f;
        #pragma unroll
        for (int t = 0; t < 6; t++) {
            v[t] = proxy[j * FEAT + lane + 32 * t];
            ss += v[t] * v[t];
        }
        #pragma unroll
        for (int o = 16; o; o >>= 1) ss += __shfl_xor_sync(0xffffffffu, ss, o);
        float inv = 1.0f / fmaxf(sqrtf(ss), 1e-12f);
        #pragma unroll
        for (int t = 0; t < 6; t++) {
            int k = lane + 32 * t;
            ((__half*)g_npTH)[packslotH(k, j, 64)] = __float2half_rn(v[t] * inv);
        }
    }
}

// ---------------- graph attention layer: warp per node, half2 math ---------
__global__ void __launch_bounds__(256) layer_kernel(
        float* __restrict__ out,
        const __half* __restrict__ fin,
        __half* __restrict__ fout,
        const int* __restrict__ src,
        const int* __restrict__ rid,
        const float* __restrict__ rval,
        int l) {
    __shared__ int4 s_meta[8 * DEG];
    int wb = threadIdx.x >> 5;
    int w = (blockIdx.x * blockDim.x + threadIdx.x) >> 5;
    int lane = threadIdx.x & 31;
    if (w >= N_NODES) return;
    int base = w * DEG;

    float att = -INFINITY;
    int ms = 0, mr = 0;
    if (lane < DEG) {
        int e = base + lane;
        ms = __ldg(src + e);
        mr = __ldg(rid + e);
        float sgn = __ldg(rval + e) < 0.f ? -1.f : 1.f;
        att = sgn * g_attW[l * R_REL + mr];
    }
    float m = att;
    #pragma unroll
    for (int o = 16; o; o >>= 1) m = fmaxf(m, __shfl_xor_sync(0xffffffffu, m, o));
    float ex = (lane < DEG) ? __expf(att - m) : 0.f;
    float s = ex;
    #pragma unroll
    for (int o = 16; o; o >>= 1) s += __shfl_xor_sync(0xffffffffu, s, o);
    float wgt = ex / s;

    if (lane < DEG)
        s_meta[wb * DEG + lane] = make_int4(ms * NODE_DIM,
                                            mr * NODE_DIM,
                                            __float_as_int(wgt), 0);
    __syncwarp();

    int half = lane >> 4;
    int q4 = (lane & 15) << 2;
    float4 acc = make_float4(0.f, 0.f, 0.f, 0.f);
    #pragma unroll 4
    for (int i = 0; i < 12; i++) {
        int4 md = s_meta[wb * DEG + 2 * i + half];
        uint2 fu = *(const uint2*)(fin + md.x + q4);
        uint2 ru = *(const uint2*)(g_nrelh + md.y + q4);
        __half2 f01 = bits2h(fu.x), f23 = bits2h(fu.y);
        __half2 r01 = bits2h(ru.x), r23 = bits2h(ru.y);
        __half2 dh = __hfma2(f23, r23, __hmul2(f01, r01));
        float d = __low2float(dh) + __high2float(dh);
        #pragma unroll
        for (int o = 8; o; o >>= 1) d += __shfl_xor_sync(0xffffffffu, d, o);
        __half2 nt2 = __float2half2_rn(-2.f * d);
        float2 v01 = __half22float2(__hfma2(nt2, r01, f01));
        float2 v23 = __half22float2(__hfma2(nt2, r23, f23));
        float we = __int_as_float(md.z);
        acc.x += we * v01.x;
        acc.y += we * v01.y;
        acc.z += we * v23.x;
        acc.w += we * v23.y;
    }
    acc.x += __shfl_xor_sync(0xffffffffu, acc.x, 16);
    acc.y += __shfl_xor_sync(0xffffffffu, acc.y, 16);
    acc.z += __shfl_xor_sync(0xffffffffu, acc.z, 16);
    acc.w += __shfl_xor_sync(0xffffffffu, acc.w, 16);

    if (half == 0) {
        float4 tv = make_float4(tanhf(acc.x), tanhf(acc.y), tanhf(acc.z), tanhf(acc.w));
        float* dst = out + (long)w * FEAT + NODE_DIM * (l + 1);
        *(float4*)(dst + q4) = tv;
        if (fout)
            *(uint2*)(fout + w * NODE_DIM + q4) =
                make_uint2(pack2h(tv.x, tv.y), pack2h(tv.z, tv.w));
    }
}

// ---------------- fp16 m16n8k16 mma helper ----------------------------------
__device__ __forceinline__ void mma16(float* d, const unsigned* a, const unsigned* b) {
    asm volatile(
        "mma.sync.aligned.m16n8k16.row.col.f32.f16.f16.f32 "
        "{%0,%1,%2,%3}, {%4,%5,%6,%7}, {%8,%9}, {%0,%1,%2,%3};\n"
        : "+f"(d[0]), "+f"(d[1]), "+f"(d[2]), "+f"(d[3])
        : "r"(a[0]), "r"(a[1]), "r"(a[2]), "r"(a[3]), "r"(b[0]), "r"(b[1]));
}

// ---------------- fused final stage (fp16 tensor-core, 96-row tile) ---------
// 512 threads = 16 warps: warp (mg, ng); mg picks 48-row half, per-warp tile
// shape (MT=3 m16-tiles x 24 n-cols) identical to the measured-best config.
#define NT 96
#define MT 3
#define SXH 100            // uint stride: 96 half2-pairs + pad
#define SPH 36             // uint stride: 32 half2-pairs + pad
__global__ void __launch_bounds__(512, 2) final_kernel(
        float* __restrict__ out,
        const float* __restrict__ gate_b) {
    extern __shared__ unsigned smem_u[];
    unsigned* s_x  = smem_u;                 // NT*SXH (o fp16 pairs, later pf)
    unsigned* s_p  = s_x + NT * SXH;         // NT*SPH (logits/probs fp16 pairs)
    float*    s_inv = (float*)(s_p + NT * SPH);  // NT

    int tid = threadIdx.x;
    int w16 = tid >> 5, lane = tid & 31;
    int ng = w16 & 7, mg = w16 >> 3;         // mg in {0,1}
    int g = lane >> 2, t = lane & 3;
    int n0 = blockIdx.x * NT;
    int rows = N_NODES - n0; if (rows > NT) rows = NT;

    // ---- load o tile -> half2 pairs ----
    for (int i = tid; i < NT * 48; i += 512) {
        int r = i / 48, q = i - r * 48;
        float4 v = (r < rows) ? *(const float4*)(out + (long)(n0 + r) * FEAT + q * 4)
                              : make_float4(0.f, 0.f, 0.f, 0.f);
        s_x[r * SXH + 2 * q]     = pack2h(v.x, v.y);
        s_x[r * SXH + 2 * q + 1] = pack2h(v.z, v.w);
    }
    __syncthreads();

    // ---- row inverse norms (6 rows per warp) ----
    for (int r = w16 * 6; r < w16 * 6 + 6; r++) {
        float ss = 0.f;
        #pragma unroll
        for (int tt = 0; tt < 3; tt++) {
            float2 v = unpk(s_x[r * SXH + lane + 32 * tt]);
            ss += v.x * v.x + v.y * v.y;
        }
        #pragma unroll
        for (int o = 16; o; o >>= 1) ss += __shfl_xor_sync(0xffffffffu, ss, o);
        if (lane == 0) s_inv[r] = 1.0f / fmaxf(sqrtf(ss), 1e-12f);
    }
    __syncthreads();

    // ---- GEMM1: logits[NT x 64] = o @ nproxy^T (12 k16-steps) ----
    {
        float d1[MT][4];
        #pragma unroll
        for (int mi = 0; mi < MT; mi++)
            #pragma unroll
            for (int q = 0; q < 4; q++) d1[mi][q] = 0.f;
        int bi = (8 * ng + g) * 4 + t;           // + kk*256
        uint2 bc = __ldg(g_npTH + bi);
        for (int kk = 0; kk < 12; kk++) {
            uint2 bn = make_uint2(0u, 0u);
            if (kk + 1 < 12) bn = __ldg(g_npTH + (kk + 1) * 256 + bi);
            #pragma unroll
            for (int mi = 0; mi < MT; mi++) {
                int r0 = 16 * (3 * mg + mi) + g;
                unsigned a[4];
                a[0] = s_x[r0 * SXH + 8 * kk + t];
                a[1] = s_x[(r0 + 8) * SXH + 8 * kk + t];
                a[2] = s_x[r0 * SXH + 8 * kk + t + 4];
                a[3] = s_x[(r0 + 8) * SXH + 8 * kk + t + 4];
                mma16(d1[mi], a, (const unsigned*)&bc);
            }
            bc = bn;
        }
        int pc = 4 * ng + t;                     // logits pair (cols 8ng+2t, +1)
        #pragma unroll
        for (int mi = 0; mi < MT; mi++) {
            int r0 = 16 * (3 * mg + mi) + g;
            float i0 = s_inv[r0], i1 = s_inv[r0 + 8];
            s_p[r0 * SPH + pc]       = pack2h(d1[mi][0] * i0, d1[mi][1] * i0);
            s_p[(r0 + 8) * SPH + pc] = pack2h(d1[mi][2] * i1, d1[mi][3] * i1);
        }
    }
    __syncthreads();

    // ---- softmax over 64 per row (6 rows per warp, 2 vals/lane) ----
    for (int r = w16 * 6; r < w16 * 6 + 6; r++) {
        float2 v = unpk(s_p[r * SPH + lane]);
        float mx = fmaxf(v.x, v.y);
        #pragma unroll
        for (int o = 16; o; o >>= 1) mx = fmaxf(mx, __shfl_xor_sync(0xffffffffu, mx, o));
        float e0 = __expf(v.x - mx), e1 = __expf(v.y - mx);
        float sm = e0 + e1;
        #pragma unroll
        for (int o = 16; o; o >>= 1) sm += __shfl_xor_sync(0xffffffffu, sm, o);
        float invs = 1.0f / sm;
        s_p[r * SPH + lane] = pack2h(e0 * invs, e1 * invs);
    }
    __syncthreads();

    // ---- GEMM2: pf = o - P @ proxy (4 k16-steps), in-place on s_x ----
    {
        float d2[3][MT][4];
        #pragma unroll
        for (int ni = 0; ni < 3; ni++)
            #pragma unroll
            for (int mi = 0; mi < MT; mi++)
                #pragma unroll
                for (int q = 0; q < 4; q++) d2[ni][mi][q] = 0.f;
        int bi = (24 * ng + g) * 4 + t;          // + ni*32 + kk*768
        uint2 bc[3], bn[3];
        #pragma unroll
        for (int ni = 0; ni < 3; ni++) bc[ni] = __ldg(g_prxH + bi + 32 * ni);
        for (int kk = 0; kk < 4; kk++) {
            if (kk + 1 < 4) {
                #pragma unroll
                for (int ni = 0; ni < 3; ni++)
                    bn[ni] = __ldg(g_prxH + (kk + 1) * 768 + bi + 32 * ni);
            }
            unsigned a[MT][4];
            #pragma unroll
            for (int mi = 0; mi < MT; mi++) {
                int r0 = 16 * (3 * mg + mi) + g;
                a[mi][0] = s_p[r0 * SPH + 8 * kk + t];
                a[mi][1] = s_p[(r0 + 8) * SPH + 8 * kk + t];
                a[mi][2] = s_p[r0 * SPH + 8 * kk + t + 4];
                a[mi][3] = s_p[(r0 + 8) * SPH + 8 * kk + t + 4];
            }
            #pragma unroll
            for (int ni = 0; ni < 3; ni++)
                #pragma unroll
                for (int mi = 0; mi < MT; mi++)
                    mma16(d2[ni][mi], a[mi], (const unsigned*)&bc[ni]);
            #pragma unroll
            for (int ni = 0; ni < 3; ni++) bc[ni] = bn[ni];
        }
        #pragma unroll
        for (int ni = 0; ni < 3; ni++) {
            int pc = 12 * ng + 4 * ni + t;       // pf pair (cols 24ng+8ni+2t, +1)
            #pragma unroll
            for (int mi = 0; mi < MT; mi++) {
                int r0 = 16 * (3 * mg + mi) + g;
                float2 o0 = unpk(s_x[r0 * SXH + pc]);
                float2 o1 = unpk(s_x[(r0 + 8) * SXH + pc]);
                s_x[r0 * SXH + pc]       = pack2h(o0.x - d2[ni][mi][0], o0.y - d2[ni][mi][1]);
                s_x[(r0 + 8) * SXH + pc] = pack2h(o1.x - d2[ni][mi][2], o1.y - d2[ni][mi][3]);
            }
        }
    }
    __syncthreads();

    // ---- GEMM3: pf @ W^T + b -> sigmoid -> blend (12 k16-steps) ----
    {
        float d3[3][MT][4];
        #pragma unroll
        for (int ni = 0; ni < 3; ni++)
            #pragma unroll
            for (int mi = 0; mi < MT; mi++)
                #pragma unroll
                for (int q = 0; q < 4; q++) d3[ni][mi][q] = 0.f;
        int bi = (24 * ng + g) * 4 + t;          // + ni*32 + kk*768
        uint2 bc[3], bn[3];
        #pragma unroll
        for (int ni = 0; ni < 3; ni++) bc[ni] = __ldg(g_WtH + bi + 32 * ni);
        #pragma unroll 2
        for (int kk = 0; kk < 12; kk++) {
            if (kk + 1 < 12) {
                #pragma unroll
                for (int ni = 0; ni < 3; ni++)
                    bn[ni] = __ldg(g_WtH + (kk + 1) * 768 + bi + 32 * ni);
            }
            unsigned a[MT][4];
            #pragma unroll
            for (int mi = 0; mi < MT; mi++) {
                int r0 = 16 * (3 * mg + mi) + g;
                a[mi][0] = s_x[r0 * SXH + 8 * kk + t];
                a[mi][1] = s_x[(r0 + 8) * SXH + 8 * kk + t];
                a[mi][2] = s_x[r0 * SXH + 8 * kk + t + 4];
                a[mi][3] = s_x[(r0 + 8) * SXH + 8 * kk + t + 4];
            }
            #pragma unroll
            for (int ni = 0; ni < 3; ni++)
                #pragma unroll
                for (int mi = 0; mi < MT; mi++)
                    mma16(d3[ni][mi], a[mi], (const unsigned*)&bc[ni]);
            #pragma unroll
            for (int ni = 0; ni < 3; ni++) bc[ni] = bn[ni];
        }
        #pragma unroll
        for (int ni = 0; ni < 3; ni++) {
            int c = 24 * ng + 8 * ni + 2 * t;
            int pc = c >> 1;                     // = 12ng + 4ni + t
            float b0 = __ldg(gate_b + c), b1 = __ldg(gate_b + c + 1);
            #pragma unroll
            for (int mi = 0; mi < MT; mi++) {
                int r0 = 16 * (3 * mg + mi) + g;
                #pragma unroll
                for (int half = 0; half < 2; half++) {
                    int r = r0 + 8 * half;
                    if (r >= rows) continue;
                    float p0 = d3[ni][mi][2 * half]     + b0;
                    float p1 = d3[ni][mi][2 * half + 1] + b1;
                    float g0 = 1.0f / (1.0f + __expf(-p0));
                    float g1 = 1.0f / (1.0f + __expf(-p1));
                    float2 o2 = *(const float2*)(out + (long)(n0 + r) * FEAT + c);
                    float2 pf = unpk(s_x[r * SXH + pc]);
                    float2 res = make_float2(g0 * o2.x + (1.0f - g0) * pf.x,
                                             g1 * o2.y + (1.0f - g1) * pf.y);
                    *(float2*)(out + (long)(n0 + r) * FEAT + c) = res;
                }
            }
        }
    }
}

extern "C" void kernel_launch(void* const* d_in, const int* in_sizes, int n_in,
                              void* d_out, int out_size) {
    const float* features     = (const float*)d_in[0];   // [N,64]
    const float* rel_emb      = (const float*)d_in[1];   // [R,64]
    const float* proxy        = (const float*)d_in[2];   // [64,192]
    const float* gate_w       = (const float*)d_in[3];   // [192,192]
    const float* gate_b       = (const float*)d_in[4];   // [192]
    const float* attn_kernels = (const float*)d_in[5];   // [2,64]
    const int*   adj          = (const int*)d_in[6];     // [2,E]
    const int*   r_index      = (const int*)d_in[7];     // [2,E]
    const float* r_val        = (const float*)d_in[8];   // [E]
    float* out = (float*)d_out;                          // [N,192]

    const int* src = adj + E_EDGES;
    const int* rid = r_index + E_EDGES;

    setup_kernel<<<TB_TANH + TB_TABS + TB_PREP, 256>>>(
        features, out, rel_emb, attn_kernels, proxy, gate_w);

    __half* fh0; cudaGetSymbolAddress((void**)&fh0, g_fh0);
    __half* fh1; cudaGetSymbolAddress((void**)&fh1, g_fh1);

    int lgrid = (N_NODES * 32 + 255) / 256;
    layer_kernel<<<lgrid, 256>>>(out, fh0, fh1, src, rid, r_val, 0);
    layer_kernel<<<lgrid, 256>>>(out, fh1, (__half*)0, src, rid, r_val, 1);

    size_t smem = (size_t)(NT * SXH + NT * SPH) * sizeof(unsigned) + NT * sizeof(float);
    cudaFuncSetAttribute(final_kernel, cudaFuncAttributeMaxDynamicSharedMemorySize, (int)smem);
    final_kernel<<<(N_NODES + NT - 1) / NT, 512, smem>>>(out, gate_b);
}

// round 16
// speedup vs baseline: 1.1316x; 1.1316x over previous
#include <cuda_runtime.h>
#include <cuda_fp16.h>
#include <cuda_bf16.h>
#include <math.h>

#define N_NODES 50000
#define NODE_DIM 64
#define DEPTH 2
#define FEAT 192           // 64*(DEPTH+1)
#define E_EDGES 1200000
#define R_REL 500
#define DEG 24

// ---------------- scratch (device globals: allocation-free) ----------------
__device__ float    g_attW[DEPTH * R_REL];      // per-relation attention logit per layer
__device__ __half   g_nrelh[R_REL * NODE_DIM];  // l2-normalized rel_emb (fp16)
__device__ __half   g_fh0[N_NODES * NODE_DIM];  // tanh(features) fp16
__device__ __half   g_fh1[N_NODES * NODE_DIM];  // layer-0 output fp16
// fp16 MMA B-fragment tables: uint2 per (k16-step, col, t): (b0,b1) halves
__device__ uint2 g_npTH[12 * 64 * 4];           // normalized proxy^T  (k=192, n=64)
__device__ uint2 g_prxH[4 * 192 * 4];           // proxy [k][n]        (k=64,  n=192)
__device__ uint2 g_WtH[12 * 192 * 4];           // gate_w^T [k][c]     (k=192, n=192)

__device__ __forceinline__ unsigned h2bits(__half2 h) {
    union { __half2 h; unsigned u; } c; c.h = h; return c.u;
}
__device__ __forceinline__ __half2 bits2h(unsigned u) {
    union { unsigned u; __half2 h; } c; c.u = u; return c.h;
}
__device__ __forceinline__ float2 unpk(unsigned u) { return __half22float2(bits2h(u)); }
__device__ __forceinline__ unsigned pack2h(float a, float b) {
    return h2bits(__float22half2_rn(make_float2(a, b)));
}
// half index inside the uint2-pair B table for element (k, c)
__device__ __forceinline__ int packslotH(int k, int c, int ncols) {
    return ((((k >> 4) * ncols + c) * 4 + ((k >> 1) & 3)) * 4)
         + (((k >> 3) & 1) * 2) + (k & 1);
}

// ---------------- fused setup: tanh + fp16 table packing + rel normalize ---
#define TB_TANH ((N_NODES * 16 + 255) / 256)
#define TB_TABS ((FEAT * FEAT + 64 * FEAT + 255) / 256)
#define TB_PREP ((564 * 32 + 255) / 256)
__global__ void setup_kernel(const float* __restrict__ features,
                             float* __restrict__ out,
                             const float* __restrict__ rel_emb,
                             const float* __restrict__ attn_kernels,
                             const float* __restrict__ proxy,
                             const float* __restrict__ gw) {
    int b = blockIdx.x;
    if (b < TB_TANH) {
        int idx = b * blockDim.x + threadIdx.x;
        if (idx >= N_NODES * 16) return;
        int i = idx >> 4;
        int j4 = (idx & 15) << 2;
        float4 v = *(const float4*)(features + i * NODE_DIM + j4);
        float4 tv = make_float4(tanhf(v.x), tanhf(v.y), tanhf(v.z), tanhf(v.w));
        *(float4*)(out + (long)i * FEAT + j4) = tv;
        *(uint2*)(g_fh0 + i * NODE_DIM + j4) =
            make_uint2(pack2h(tv.x, tv.y), pack2h(tv.z, tv.w));
        return;
    }
    if (b < TB_TANH + TB_TABS) {
        int idx = (b - TB_TANH) * blockDim.x + threadIdx.x;
        if (idx < FEAT * FEAT) {
            int k = idx / FEAT, c = idx - k * FEAT;
            ((__half*)g_WtH)[packslotH(k, c, FEAT)] = __float2half_rn(gw[c * FEAT + k]);
        } else if (idx < FEAT * FEAT + 64 * FEAT) {
            int j = idx - FEAT * FEAT;
            int k = j / FEAT, c = j - k * FEAT;
            ((__half*)g_prxH)[packslotH(k, c, FEAT)] = __float2half_rn(proxy[k * FEAT + c]);
        }
        return;
    }
    int w = ((b - TB_TANH - TB_TABS) * blockDim.x + threadIdx.x) >> 5;
    int lane = threadIdx.x & 31;
    if (w < R_REL) {
        float2 v = ((const float2*)(rel_emb + w * NODE_DIM))[lane];
        float ss = v.x * v.x + v.y * v.y;
        #pragma unroll
        for (int o = 16; o; o >>= 1) ss += __shfl_xor_sync(0xffffffffu, ss, o);
        float inv = 1.0f / fmaxf(sqrtf(ss), 1e-12f);
        float2 nv = make_float2(v.x * inv, v.y * inv);
        ((__half2*)(g_nrelh + w * NODE_DIM))[lane] = __float22half2_rn(nv);
        float2 a0 = ((const float2*)attn_kernels)[lane];
        float2 a1 = ((const float2*)(attn_kernels + NODE_DIM))[lane];
        float d0 = nv.x * a0.x + nv.y * a0.y;
        float d1 = nv.x * a1.x + nv.y * a1.y;
        #pragma unroll
        for (int o = 16; o; o >>= 1) {
            d0 += __shfl_xor_sync(0xffffffffu, d0, o);
            d1 += __shfl_xor_sync(0xffffffffu, d1, o);
        }
        if (lane == 0) { g_attW[w] = d0; g_attW[R_REL + w] = d1; }
    } else if (w < R_REL + 64) {
        int j = w - R_REL;
        float v[6];
        float ss = 0.f;
        #pragma unroll
        for (int t = 0; t < 6; t++) {
            v[t] = proxy[j * FEAT + lane + 32 * t];
            ss += v[t] * v[t];
        }
        #pragma unroll
        for (int o = 16; o; o >>= 1) ss += __shfl_xor_sync(0xffffffffu, ss, o);
        float inv = 1.0f / fmaxf(sqrtf(ss), 1e-12f);
        #pragma unroll
        for (int t = 0; t < 6; t++) {
            int k = lane + 32 * t;
            ((__half*)g_npTH)[packslotH(k, j, 64)] = __float2half_rn(v[t] * inv);
        }
    }
}

// ---------------- graph attention layer: warp per node, half2 math ---------
__global__ void __launch_bounds__(256) layer_kernel(
        float* __restrict__ out,
        const __half* __restrict__ fin,
        __half* __restrict__ fout,
        const int* __restrict__ src,
        const int* __restrict__ rid,
        const float* __restrict__ rval,
        int l) {
    __shared__ int4 s_meta[8 * DEG];
    int wb = threadIdx.x >> 5;
    int w = (blockIdx.x * blockDim.x + threadIdx.x) >> 5;
    int lane = threadIdx.x & 31;
    if (w >= N_NODES) return;
    int base = w * DEG;

    float att = -INFINITY;
    int ms = 0, mr = 0;
    if (lane < DEG) {
        int e = base + lane;
        ms = __ldg(src + e);
        mr = __ldg(rid + e);
        float sgn = __ldg(rval + e) < 0.f ? -1.f : 1.f;
        att = sgn * g_attW[l * R_REL + mr];
    }
    float m = att;
    #pragma unroll
    for (int o = 16; o; o >>= 1) m = fmaxf(m, __shfl_xor_sync(0xffffffffu, m, o));
    float ex = (lane < DEG) ? __expf(att - m) : 0.f;
    float s = ex;
    #pragma unroll
    for (int o = 16; o; o >>= 1) s += __shfl_xor_sync(0xffffffffu, s, o);
    float wgt = ex / s;

    if (lane < DEG)
        s_meta[wb * DEG + lane] = make_int4(ms * NODE_DIM,
                                            mr * NODE_DIM,
                                            __float_as_int(wgt), 0);
    __syncwarp();

    int half = lane >> 4;
    int q4 = (lane & 15) << 2;
    float4 acc = make_float4(0.f, 0.f, 0.f, 0.f);
    #pragma unroll 4
    for (int i = 0; i < 12; i++) {
        int4 md = s_meta[wb * DEG + 2 * i + half];
        uint2 fu = *(const uint2*)(fin + md.x + q4);
        uint2 ru = *(const uint2*)(g_nrelh + md.y + q4);
        __half2 f01 = bits2h(fu.x), f23 = bits2h(fu.y);
        __half2 r01 = bits2h(ru.x), r23 = bits2h(ru.y);
        __half2 dh = __hfma2(f23, r23, __hmul2(f01, r01));
        float d = __low2float(dh) + __high2float(dh);
        #pragma unroll
        for (int o = 8; o; o >>= 1) d += __shfl_xor_sync(0xffffffffu, d, o);
        __half2 nt2 = __float2half2_rn(-2.f * d);
        float2 v01 = __half22float2(__hfma2(nt2, r01, f01));
        float2 v23 = __half22float2(__hfma2(nt2, r23, f23));
        float we = __int_as_float(md.z);
        acc.x += we * v01.x;
        acc.y += we * v01.y;
        acc.z += we * v23.x;
        acc.w += we * v23.y;
    }
    acc.x += __shfl_xor_sync(0xffffffffu, acc.x, 16);
    acc.y += __shfl_xor_sync(0xffffffffu, acc.y, 16);
    acc.z += __shfl_xor_sync(0xffffffffu, acc.z, 16);
    acc.w += __shfl_xor_sync(0xffffffffu, acc.w, 16);

    if (half == 0) {
        float4 tv = make_float4(tanhf(acc.x), tanhf(acc.y), tanhf(acc.z), tanhf(acc.w));
        float* dst = out + (long)w * FEAT + NODE_DIM * (l + 1);
        *(float4*)(dst + q4) = tv;
        if (fout)
            *(uint2*)(fout + w * NODE_DIM + q4) =
                make_uint2(pack2h(tv.x, tv.y), pack2h(tv.z, tv.w));
    }
}

// ---------------- fp16 m16n8k16 mma + ldmatrix helpers ----------------------
__device__ __forceinline__ void mma16(float* d, const unsigned* a, const unsigned* b) {
    asm volatile(
        "mma.sync.aligned.m16n8k16.row.col.f32.f16.f16.f32 "
        "{%0,%1,%2,%3}, {%4,%5,%6,%7}, {%8,%9}, {%0,%1,%2,%3};\n"
        : "+f"(d[0]), "+f"(d[1]), "+f"(d[2]), "+f"(d[3])
        : "r"(a[0]), "r"(a[1]), "r"(a[2]), "r"(a[3]), "r"(b[0]), "r"(b[1]));
}
__device__ __forceinline__ void ldsm4(unsigned* r, unsigned saddr) {
    asm volatile(
        "ldmatrix.sync.aligned.m8n8.x4.shared.b16 {%0,%1,%2,%3}, [%4];\n"
        : "=r"(r[0]), "=r"(r[1]), "=r"(r[2]), "=r"(r[3])
        : "r"(saddr));
}

// ---------------- fused final stage (fp16 tensor-core + ldmatrix) -----------
// NT=48 / 256 threads / 4 CTAs per SM (measured-best config).
#define NT 48
#define MT 3
#define SXH 100            // uint stride: 96 half2-pairs + pad (400 B)
#define SPH 36             // uint stride: 32 half2-pairs + pad (144 B)
__global__ void __launch_bounds__(256, 4) final_kernel(
        float* __restrict__ out,
        const float* __restrict__ gate_b) {
    extern __shared__ unsigned smem_u[];
    unsigned* s_x  = smem_u;                 // NT*SXH (o fp16 pairs, later pf)
    unsigned* s_p  = s_x + NT * SXH;         // NT*SPH (logits/probs fp16 pairs)
    float*    s_inv = (float*)(s_p + NT * SPH);  // NT

    int tid = threadIdx.x;
    int w = tid >> 5, lane = tid & 31;
    int g = lane >> 2, t = lane & 3;
    int n0 = blockIdx.x * NT;
    int rows = N_NODES - n0; if (rows > NT) rows = NT;

    // ldmatrix per-lane addressing: matrices (a0..a3) = (r, k), (r+8, k), (r, k+8h), (r+8, k+8h)
    int rowoff = (lane & 7) + ((lane >> 3) & 1) * 8;   // row within 16-row tile
    int kext = (lane >> 4) * 16;                       // byte offset for k-halves 8..15
    unsigned sxs = (unsigned)__cvta_generic_to_shared(s_x);
    unsigned sps = (unsigned)__cvta_generic_to_shared(s_p);
    unsigned axb[MT], apb[MT];
    #pragma unroll
    for (int mi = 0; mi < MT; mi++) {
        axb[mi] = sxs + (unsigned)(((16 * mi + rowoff) * SXH) * 4 + kext);
        apb[mi] = sps + (unsigned)(((16 * mi + rowoff) * SPH) * 4 + kext);
    }

    // ---- load o tile -> half2 pairs ----
    for (int i = tid; i < NT * 48; i += 256) {
        int r = i / 48, q = i - r * 48;
        float4 v = (r < rows) ? *(const float4*)(out + (long)(n0 + r) * FEAT + q * 4)
                              : make_float4(0.f, 0.f, 0.f, 0.f);
        s_x[r * SXH + 2 * q]     = pack2h(v.x, v.y);
        s_x[r * SXH + 2 * q + 1] = pack2h(v.z, v.w);
    }
    __syncthreads();

    // ---- row inverse norms (6 rows per warp) ----
    for (int r = w * 6; r < w * 6 + 6; r++) {
        float ss = 0.f;
        #pragma unroll
        for (int tt = 0; tt < 3; tt++) {
            float2 v = unpk(s_x[r * SXH + lane + 32 * tt]);
            ss += v.x * v.x + v.y * v.y;
        }
        #pragma unroll
        for (int o = 16; o; o >>= 1) ss += __shfl_xor_sync(0xffffffffu, ss, o);
        if (lane == 0) s_inv[r] = 1.0f / fmaxf(sqrtf(ss), 1e-12f);
    }
    __syncthreads();

    // ---- GEMM1: logits[NT x 64] = o @ nproxy^T (12 k16-steps) ----
    {
        float d1[MT][4];
        #pragma unroll
        for (int mi = 0; mi < MT; mi++)
            #pragma unroll
            for (int q = 0; q < 4; q++) d1[mi][q] = 0.f;
        int bi = (8 * w + g) * 4 + t;            // + kk*256
        uint2 bc = __ldg(g_npTH + bi);
        for (int kk = 0; kk < 12; kk++) {
            uint2 bn = make_uint2(0u, 0u);
            if (kk + 1 < 12) bn = __ldg(g_npTH + (kk + 1) * 256 + bi);
            #pragma unroll
            for (int mi = 0; mi < MT; mi++) {
                unsigned a[4];
                ldsm4(a, axb[mi] + kk * 32);
                mma16(d1[mi], a, (const unsigned*)&bc);
            }
            bc = bn;
        }
        int pc = 4 * w + t;                      // logits pair (cols 8w+2t, +1)
        #pragma unroll
        for (int mi = 0; mi < MT; mi++) {
            int r0 = 16 * mi + g;
            float i0 = s_inv[r0], i1 = s_inv[r0 + 8];
            s_p[r0 * SPH + pc]       = pack2h(d1[mi][0] * i0, d1[mi][1] * i0);
            s_p[(r0 + 8) * SPH + pc] = pack2h(d1[mi][2] * i1, d1[mi][3] * i1);
        }
    }
    __syncthreads();

    // ---- softmax over 64 per row (6 rows per warp, 2 vals/lane) ----
    for (int r = w * 6; r < w * 6 + 6; r++) {
        float2 v = unpk(s_p[r * SPH + lane]);
        float mx = fmaxf(v.x, v.y);
        #pragma unroll
        for (int o = 16; o; o >>= 1) mx = fmaxf(mx, __shfl_xor_sync(0xffffffffu, mx, o));
        float e0 = __expf(v.x - mx), e1 = __expf(v.y - mx);
        float sm = e0 + e1;
        #pragma unroll
        for (int o = 16; o; o >>= 1) sm += __shfl_xor_sync(0xffffffffu, sm, o);
        float invs = 1.0f / sm;
        s_p[r * SPH + lane] = pack2h(e0 * invs, e1 * invs);
    }
    __syncthreads();

    // ---- GEMM2: pf = o - P @ proxy (4 k16-steps), in-place on s_x ----
    {
        float d2[3][MT][4];
        #pragma unroll
        for (int ni = 0; ni < 3; ni++)
            #pragma unroll
            for (int mi = 0; mi < MT; mi++)
                #pragma unroll
                for (int q = 0; q < 4; q++) d2[ni][mi][q] = 0.f;
        int bi = (24 * w + g) * 4 + t;           // + ni*32 + kk*768
        uint2 bc[3], bn[3];
        #pragma unroll
        for (int ni = 0; ni < 3; ni++) bc[ni] = __ldg(g_prxH + bi + 32 * ni);
        for (int kk = 0; kk < 4; kk++) {
            if (kk + 1 < 4) {
                #pragma unroll
                for (int ni = 0; ni < 3; ni++)
                    bn[ni] = __ldg(g_prxH + (kk + 1) * 768 + bi + 32 * ni);
            }
            unsigned a[MT][4];
            #pragma unroll
            for (int mi = 0; mi < MT; mi++) ldsm4(a[mi], apb[mi] + kk * 32);
            #pragma unroll
            for (int ni = 0; ni < 3; ni++)
                #pragma unroll
                for (int mi = 0; mi < MT; mi++)
                    mma16(d2[ni][mi], a[mi], (const unsigned*)&bc[ni]);
            #pragma unroll
            for (int ni = 0; ni < 3; ni++) bc[ni] = bn[ni];
        }
        #pragma unroll
        for (int ni = 0; ni < 3; ni++) {
            int pc = 12 * w + 4 * ni + t;        // pf pair (cols 24w+8ni+2t, +1)
            #pragma unroll
            for (int mi = 0; mi < MT; mi++) {
                int r0 = 16 * mi + g;
                float2 o0 = unpk(s_x[r0 * SXH + pc]);
                float2 o1 = unpk(s_x[(r0 + 8) * SXH + pc]);
                s_x[r0 * SXH + pc]       = pack2h(o0.x - d2[ni][mi][0], o0.y - d2[ni][mi][1]);
                s_x[(r0 + 8) * SXH + pc] = pack2h(o1.x - d2[ni][mi][2], o1.y - d2[ni][mi][3]);
            }
        }
    }
    __syncthreads();

    // ---- GEMM3: pf @ W^T + b -> sigmoid -> blend (12 k16-steps) ----
    {
        float d3[3][MT][4];
        #pragma unroll
        for (int ni = 0; ni < 3; ni++)
            #pragma unroll
            for (int mi = 0; mi < MT; mi++)
                #pragma unroll
                for (int q = 0; q < 4; q++) d3[ni][mi][q] = 0.f;
        int bi = (24 * w + g) * 4 + t;           // + ni*32 + kk*768
        uint2 bc[3], bn[3];
        #pragma unroll
        for (int ni = 0; ni < 3; ni++) bc[ni] = __ldg(g_WtH + bi + 32 * ni);
        #pragma unroll 2
        for (int kk = 0; kk < 12; kk++) {
            if (kk + 1 < 12) {
                #pragma unroll
                for (int ni = 0; ni < 3; ni++)
                    bn[ni] = __ldg(g_WtH + (kk + 1) * 768 + bi + 32 * ni);
            }
            unsigned a[MT][4];
            #pragma unroll
            for (int mi = 0; mi < MT; mi++) ldsm4(a[mi], axb[mi] + kk * 32);
            #pragma unroll
            for (int ni = 0; ni < 3; ni++)
                #pragma unroll
                for (int mi = 0; mi < MT; mi++)
                    mma16(d3[ni][mi], a[mi], (const unsigned*)&bc[ni]);
            #pragma unroll
            for (int ni = 0; ni < 3; ni++) bc[ni] = bn[ni];
        }
        #pragma unroll
        for (int ni = 0; ni < 3; ni++) {
            int c = 24 * w + 8 * ni + 2 * t;
            int pc = c >> 1;                     // = 12w + 4ni + t
            float b0 = __ldg(gate_b + c), b1 = __ldg(gate_b + c + 1);
            #pragma unroll
            for (int mi = 0; mi < MT; mi++) {
                int r0 = 16 * mi + g;
                #pragma unroll
                for (int half = 0; half < 2; half++) {
                    int r = r0 + 8 * half;
                    if (r >= rows) continue;
                    float p0 = d3[ni][mi][2 * half]     + b0;
                    float p1 = d3[ni][mi][2 * half + 1] + b1;
                    float g0 = 1.0f / (1.0f + __expf(-p0));
                    float g1 = 1.0f / (1.0f + __expf(-p1));
                    float2 o2 = *(const float2*)(out + (long)(n0 + r) * FEAT + c);
                    float2 pf = unpk(s_x[r * SXH + pc]);
                    float2 res = make_float2(g0 * o2.x + (1.0f - g0) * pf.x,
                                             g1 * o2.y + (1.0f - g1) * pf.y);
                    *(float2*)(out + (long)(n0 + r) * FEAT + c) = res;
                }
            }
        }
    }
}

extern "C" void kernel_launch(void* const* d_in, const int* in_sizes, int n_in,
                              void* d_out, int out_size) {
    const float* features     = (const float*)d_in[0];   // [N,64]
    const float* rel_emb      = (const float*)d_in[1];   // [R,64]
    const float* proxy        = (const float*)d_in[2];   // [64,192]
    const float* gate_w       = (const float*)d_in[3];   // [192,192]
    const float* gate_b       = (const float*)d_in[4];   // [192]
    const float* attn_kernels = (const float*)d_in[5];   // [2,64]
    const int*   adj          = (const int*)d_in[6];     // [2,E]
    const int*   r_index      = (const int*)d_in[7];     // [2,E]
    const float* r_val        = (const float*)d_in[8];   // [E]
    float* out = (float*)d_out;                          // [N,192]

    const int* src = adj + E_EDGES;
    const int* rid = r_index + E_EDGES;

    setup_kernel<<<TB_TANH + TB_TABS + TB_PREP, 256>>>(
        features, out, rel_emb, attn_kernels, proxy, gate_w);

    __half* fh0; cudaGetSymbolAddress((void**)&fh0, g_fh0);
    __half* fh1; cudaGetSymbolAddress((void**)&fh1, g_fh1);

    int lgrid = (N_NODES * 32 + 255) / 256;
    layer_kernel<<<lgrid, 256>>>(out, fh0, fh1, src, rid, r_val, 0);
    layer_kernel<<<lgrid, 256>>>(out, fh1, (__half*)0, src, rid, r_val, 1);

    size_t smem = (size_t)(NT * SXH + NT * SPH) * sizeof(unsigned) + NT * sizeof(float);
    cudaFuncSetAttribute(final_kernel, cudaFuncAttributeMaxDynamicSharedMemorySize, (int)smem);
    final_kernel<<<(N_NODES + NT - 1) / NT, 256, smem>>>(out, gate_b);
}

// round 17
// speedup vs baseline: 1.1781x; 1.0411x over previous
#include <cuda_runtime.h>
#include <cuda_fp16.h>
#include <cuda_bf16.h>
#include <math.h>

#define N_NODES 50000
#define NODE_DIM 64
#define DEPTH 2
#define FEAT 192           // 64*(DEPTH+1)
#define E_EDGES 1200000
#define R_REL 500
#define DEG 24

// ---------------- scratch (device globals: allocation-free) ----------------
__device__ float    g_attW[DEPTH * R_REL];      // per-relation attention logit per layer
__device__ __half   g_nrelh[R_REL * NODE_DIM];  // l2-normalized rel_emb (fp16)
__device__ __half   g_fh0[N_NODES * NODE_DIM];  // tanh(features) fp16
__device__ __half   g_fh1[N_NODES * NODE_DIM];  // layer-0 output fp16
// fp16 MMA B-fragment tables: uint2 per (k16-step, col, t): (b0,b1) halves
__device__ uint2 g_npTH[12 * 64 * 4];           // normalized proxy^T  (k=192, n=64)
__device__ uint2 g_prxH[4 * 192 * 4];           // proxy [k][n]        (k=64,  n=192)
__device__ uint2 g_WtH[12 * 192 * 4];           // gate_w^T [k][c]     (k=192, n=192)

__device__ __forceinline__ unsigned h2bits(__half2 h) {
    union { __half2 h; unsigned u; } c; c.h = h; return c.u;
}
__device__ __forceinline__ __half2 bits2h(unsigned u) {
    union { unsigned u; __half2 h; } c; c.u = u; return c.h;
}
__device__ __forceinline__ float2 unpk(unsigned u) { return __half22float2(bits2h(u)); }
__device__ __forceinline__ unsigned pack2h(float a, float b) {
    return h2bits(__float22half2_rn(make_float2(a, b)));
}
// half index inside the uint2-pair B table for element (k, c)
__device__ __forceinline__ int packslotH(int k, int c, int ncols) {
    return ((((k >> 4) * ncols + c) * 4 + ((k >> 1) & 3)) * 4)
         + (((k >> 3) & 1) * 2) + (k & 1);
}

// ---------------- fused setup: tanh + fp16 table packing + rel normalize ---
#define TB_TANH ((N_NODES * 16 + 255) / 256)
#define TB_TABS ((FEAT * FEAT + 64 * FEAT + 255) / 256)
#define TB_PREP ((564 * 32 + 255) / 256)
__global__ void setup_kernel(const float* __restrict__ features,
                             float* __restrict__ out,
                             const float* __restrict__ rel_emb,
                             const float* __restrict__ attn_kernels,
                             const float* __restrict__ proxy,
                             const float* __restrict__ gw) {
    int b = blockIdx.x;
    if (b < TB_TANH) {
        int idx = b * blockDim.x + threadIdx.x;
        if (idx >= N_NODES * 16) return;
        int i = idx >> 4;
        int j4 = (idx & 15) << 2;
        float4 v = *(const float4*)(features + i * NODE_DIM + j4);
        float4 tv = make_float4(tanhf(v.x), tanhf(v.y), tanhf(v.z), tanhf(v.w));
        *(float4*)(out + (long)i * FEAT + j4) = tv;
        *(uint2*)(g_fh0 + i * NODE_DIM + j4) =
            make_uint2(pack2h(tv.x, tv.y), pack2h(tv.z, tv.w));
        return;
    }
    if (b < TB_TANH + TB_TABS) {
        int idx = (b - TB_TANH) * blockDim.x + threadIdx.x;
        if (idx < FEAT * FEAT) {
            int k = idx / FEAT, c = idx - k * FEAT;
            ((__half*)g_WtH)[packslotH(k, c, FEAT)] = __float2half_rn(gw[c * FEAT + k]);
        } else if (idx < FEAT * FEAT + 64 * FEAT) {
            int j = idx - FEAT * FEAT;
            int k = j / FEAT, c = j - k * FEAT;
            ((__half*)g_prxH)[packslotH(k, c, FEAT)] = __float2half_rn(proxy[k * FEAT + c]);
        }
        return;
    }
    int w = ((b - TB_TANH - TB_TABS) * blockDim.x + threadIdx.x) >> 5;
    int lane = threadIdx.x & 31;
    if (w < R_REL) {
        float2 v = ((const float2*)(rel_emb + w * NODE_DIM))[lane];
        float ss = v.x * v.x + v.y * v.y;
        #pragma unroll
        for (int o = 16; o; o >>= 1) ss += __shfl_xor_sync(0xffffffffu, ss, o);
        float inv = 1.0f / fmaxf(sqrtf(ss), 1e-12f);
        float2 nv = make_float2(v.x * inv, v.y * inv);
        ((__half2*)(g_nrelh + w * NODE_DIM))[lane] = __float22half2_rn(nv);
        float2 a0 = ((const float2*)attn_kernels)[lane];
        float2 a1 = ((const float2*)(attn_kernels + NODE_DIM))[lane];
        float d0 = nv.x * a0.x + nv.y * a0.y;
        float d1 = nv.x * a1.x + nv.y * a1.y;
        #pragma unroll
        for (int o = 16; o; o >>= 1) {
            d0 += __shfl_xor_sync(0xffffffffu, d0, o);
            d1 += __shfl_xor_sync(0xffffffffu, d1, o);
        }
        if (lane == 0) { g_attW[w] = d0; g_attW[R_REL + w] = d1; }
    } else if (w < R_REL + 64) {
        int j = w - R_REL;
        float v[6];
        float ss = 0.f;
        #pragma unroll
        for (int t = 0; t < 6; t++) {
            v[t] = proxy[j * FEAT + lane + 32 * t];
            ss += v[t] * v[t];
        }
        #pragma unroll
        for (int o = 16; o; o >>= 1) ss += __shfl_xor_sync(0xffffffffu, ss, o);
        float inv = 1.0f / fmaxf(sqrtf(ss), 1e-12f);
        #pragma unroll
        for (int t = 0; t < 6; t++) {
            int k = lane + 32 * t;
            ((__half*)g_npTH)[packslotH(k, j, 64)] = __float2half_rn(v[t] * inv);
        }
    }
}

// ---------------- graph attention layer: quarter-warp edges, fp16 ----------
// 4 edges per iteration: 8 lanes x 8 dims (one uint4) per edge.
__global__ void __launch_bounds__(256) layer_kernel(
        float* __restrict__ out,
        const __half* __restrict__ fin,
        __half* __restrict__ fout,
        const int* __restrict__ src,
        const int* __restrict__ rid,
        const float* __restrict__ rval,
        int l) {
    __shared__ int4 s_meta[8 * DEG];
    int wb = threadIdx.x >> 5;
    int w = (blockIdx.x * blockDim.x + threadIdx.x) >> 5;
    int lane = threadIdx.x & 31;
    if (w >= N_NODES) return;
    int base = w * DEG;

    float att = -INFINITY;
    int ms = 0, mr = 0;
    if (lane < DEG) {
        int e = base + lane;
        ms = __ldg(src + e);
        mr = __ldg(rid + e);
        float sgn = __ldg(rval + e) < 0.f ? -1.f : 1.f;
        att = sgn * g_attW[l * R_REL + mr];
    }
    float m = att;
    #pragma unroll
    for (int o = 16; o; o >>= 1) m = fmaxf(m, __shfl_xor_sync(0xffffffffu, m, o));
    float ex = (lane < DEG) ? __expf(att - m) : 0.f;
    float s = ex;
    #pragma unroll
    for (int o = 16; o; o >>= 1) s += __shfl_xor_sync(0xffffffffu, s, o);
    float wgt = ex / s;

    if (lane < DEG)
        s_meta[wb * DEG + lane] = make_int4(ms * NODE_DIM,
                                            mr * NODE_DIM,
                                            __float_as_int(wgt), 0);
    __syncwarp();

    int grp = lane >> 3;           // edge within the quad
    int q8 = (lane & 7) << 3;      // dims [q8, q8+8)
    float acc[8];
    #pragma unroll
    for (int j = 0; j < 8; j++) acc[j] = 0.f;

    #pragma unroll
    for (int i = 0; i < 6; i++) {
        int4 md = s_meta[wb * DEG + 4 * i + grp];
        uint4 fu = *(const uint4*)(fin + md.x + q8);
        uint4 ru = *(const uint4*)(g_nrelh + md.y + q8);
        __half2 f0 = bits2h(fu.x), f1 = bits2h(fu.y), f2 = bits2h(fu.z), f3 = bits2h(fu.w);
        __half2 r0 = bits2h(ru.x), r1 = bits2h(ru.y), r2 = bits2h(ru.z), r3 = bits2h(ru.w);
        __half2 dh = __hmul2(f0, r0);
        dh = __hfma2(f1, r1, dh);
        dh = __hfma2(f2, r2, dh);
        dh = __hfma2(f3, r3, dh);
        float d = __low2float(dh) + __high2float(dh);
        d += __shfl_xor_sync(0xffffffffu, d, 1);
        d += __shfl_xor_sync(0xffffffffu, d, 2);
        d += __shfl_xor_sync(0xffffffffu, d, 4);
        __half2 nt2 = __float2half2_rn(-2.f * d);
        float2 v0 = __half22float2(__hfma2(nt2, r0, f0));
        float2 v1 = __half22float2(__hfma2(nt2, r1, f1));
        float2 v2 = __half22float2(__hfma2(nt2, r2, f2));
        float2 v3 = __half22float2(__hfma2(nt2, r3, f3));
        float we = __int_as_float(md.z);
        acc[0] += we * v0.x;  acc[1] += we * v0.y;
        acc[2] += we * v1.x;  acc[3] += we * v1.y;
        acc[4] += we * v2.x;  acc[5] += we * v2.y;
        acc[6] += we * v3.x;  acc[7] += we * v3.y;
    }
    // combine the 4 groups
    #pragma unroll
    for (int o = 8; o <= 16; o <<= 1)
        #pragma unroll
        for (int j = 0; j < 8; j++)
            acc[j] += __shfl_xor_sync(0xffffffffu, acc[j], o);

    if (grp == 0) {
        float tv[8];
        #pragma unroll
        for (int j = 0; j < 8; j++) tv[j] = tanhf(acc[j]);
        float* dst = out + (long)w * FEAT + NODE_DIM * (l + 1) + q8;
        *(float4*)dst       = make_float4(tv[0], tv[1], tv[2], tv[3]);
        *(float4*)(dst + 4) = make_float4(tv[4], tv[5], tv[6], tv[7]);
        if (fout)
            *(uint4*)(fout + w * NODE_DIM + q8) =
                make_uint4(pack2h(tv[0], tv[1]), pack2h(tv[2], tv[3]),
                           pack2h(tv[4], tv[5]), pack2h(tv[6], tv[7]));
    }
}

// ---------------- fp16 m16n8k16 mma + ldmatrix helpers ----------------------
__device__ __forceinline__ void mma16(float* d, const unsigned* a, const unsigned* b) {
    asm volatile(
        "mma.sync.aligned.m16n8k16.row.col.f32.f16.f16.f32 "
        "{%0,%1,%2,%3}, {%4,%5,%6,%7}, {%8,%9}, {%0,%1,%2,%3};\n"
        : "+f"(d[0]), "+f"(d[1]), "+f"(d[2]), "+f"(d[3])
        : "r"(a[0]), "r"(a[1]), "r"(a[2]), "r"(a[3]), "r"(b[0]), "r"(b[1]));
}
__device__ __forceinline__ void ldsm4(unsigned* r, unsigned saddr) {
    asm volatile(
        "ldmatrix.sync.aligned.m8n8.x4.shared.b16 {%0,%1,%2,%3}, [%4];\n"
        : "=r"(r[0]), "=r"(r[1]), "=r"(r[2]), "=r"(r[3])
        : "r"(saddr));
}

// ---------------- fused final stage (fp16 tensor-core + ldmatrix) -----------
#define NT 48
#define MT 3
#define SXH 100            // uint stride: 96 half2-pairs + pad (400 B)
#define SPH 36             // uint stride: 32 half2-pairs + pad (144 B)
__global__ void __launch_bounds__(256, 4) final_kernel(
        float* __restrict__ out,
        const float* __restrict__ gate_b) {
    extern __shared__ unsigned smem_u[];
    unsigned* s_x  = smem_u;                 // NT*SXH (o fp16 pairs, later pf)
    unsigned* s_p  = s_x + NT * SXH;         // NT*SPH (logits/probs fp16 pairs)
    float*    s_inv = (float*)(s_p + NT * SPH);  // NT

    int tid = threadIdx.x;
    int w = tid >> 5, lane = tid & 31;
    int g = lane >> 2, t = lane & 3;
    int n0 = blockIdx.x * NT;
    int rows = N_NODES - n0; if (rows > NT) rows = NT;

    int rowoff = (lane & 7) + ((lane >> 3) & 1) * 8;
    int kext = (lane >> 4) * 16;
    unsigned sxs = (unsigned)__cvta_generic_to_shared(s_x);
    unsigned sps = (unsigned)__cvta_generic_to_shared(s_p);
    unsigned axb[MT], apb[MT];
    #pragma unroll
    for (int mi = 0; mi < MT; mi++) {
        axb[mi] = sxs + (unsigned)(((16 * mi + rowoff) * SXH) * 4 + kext);
        apb[mi] = sps + (unsigned)(((16 * mi + rowoff) * SPH) * 4 + kext);
    }

    for (int i = tid; i < NT * 48; i += 256) {
        int r = i / 48, q = i - r * 48;
        float4 v = (r < rows) ? *(const float4*)(out + (long)(n0 + r) * FEAT + q * 4)
                              : make_float4(0.f, 0.f, 0.f, 0.f);
        s_x[r * SXH + 2 * q]     = pack2h(v.x, v.y);
        s_x[r * SXH + 2 * q + 1] = pack2h(v.z, v.w);
    }
    __syncthreads();

    for (int r = w * 6; r < w * 6 + 6; r++) {
        float ss = 0.f;
        #pragma unroll
        for (int tt = 0; tt < 3; tt++) {
            float2 v = unpk(s_x[r * SXH + lane + 32 * tt]);
            ss += v.x * v.x + v.y * v.y;
        }
        #pragma unroll
        for (int o = 16; o; o >>= 1) ss += __shfl_xor_sync(0xffffffffu, ss, o);
        if (lane == 0) s_inv[r] = 1.0f / fmaxf(sqrtf(ss), 1e-12f);
    }
    __syncthreads();

    // ---- GEMM1: logits[NT x 64] = o @ nproxy^T (12 k16-steps) ----
    {
        float d1[MT][4];
        #pragma unroll
        for (int mi = 0; mi < MT; mi++)
            #pragma unroll
            for (int q = 0; q < 4; q++) d1[mi][q] = 0.f;
        int bi = (8 * w + g) * 4 + t;
        uint2 bc = __ldg(g_npTH + bi);
        for (int kk = 0; kk < 12; kk++) {
            uint2 bn = make_uint2(0u, 0u);
            if (kk + 1 < 12) bn = __ldg(g_npTH + (kk + 1) * 256 + bi);
            #pragma unroll
            for (int mi = 0; mi < MT; mi++) {
                unsigned a[4];
                ldsm4(a, axb[mi] + kk * 32);
                mma16(d1[mi], a, (const unsigned*)&bc);
            }
            bc = bn;
        }
        int pc = 4 * w + t;
        #pragma unroll
        for (int mi = 0; mi < MT; mi++) {
            int r0 = 16 * mi + g;
            float i0 = s_inv[r0], i1 = s_inv[r0 + 8];
            s_p[r0 * SPH + pc]       = pack2h(d1[mi][0] * i0, d1[mi][1] * i0);
            s_p[(r0 + 8) * SPH + pc] = pack2h(d1[mi][2] * i1, d1[mi][3] * i1);
        }
    }
    __syncthreads();

    for (int r = w * 6; r < w * 6 + 6; r++) {
        float2 v = unpk(s_p[r * SPH + lane]);
        float mx = fmaxf(v.x, v.y);
        #pragma unroll
        for (int o = 16; o; o >>= 1) mx = fmaxf(mx, __shfl_xor_sync(0xffffffffu, mx, o));
        float e0 = __expf(v.x - mx), e1 = __expf(v.y - mx);
        float sm = e0 + e1;
        #pragma unroll
        for (int o = 16; o; o >>= 1) sm += __shfl_xor_sync(0xffffffffu, sm, o);
        float invs = 1.0f / sm;
        s_p[r * SPH + lane] = pack2h(e0 * invs, e1 * invs);
    }
    __syncthreads();

    // ---- GEMM2: pf = o - P @ proxy (4 k16-steps), in-place on s_x ----
    {
        float d2[3][MT][4];
        #pragma unroll
        for (int ni = 0; ni < 3; ni++)
            #pragma unroll
            for (int mi = 0; mi < MT; mi++)
                #pragma unroll
                for (int q = 0; q < 4; q++) d2[ni][mi][q] = 0.f;
        int bi = (24 * w + g) * 4 + t;
        uint2 bc[3], bn[3];
        #pragma unroll
        for (int ni = 0; ni < 3; ni++) bc[ni] = __ldg(g_prxH + bi + 32 * ni);
        for (int kk = 0; kk < 4; kk++) {
            if (kk + 1 < 4) {
                #pragma unroll
                for (int ni = 0; ni < 3; ni++)
                    bn[ni] = __ldg(g_prxH + (kk + 1) * 768 + bi + 32 * ni);
            }
            unsigned a[MT][4];
            #pragma unroll
            for (int mi = 0; mi < MT; mi++) ldsm4(a[mi], apb[mi] + kk * 32);
            #pragma unroll
            for (int ni = 0; ni < 3; ni++)
                #pragma unroll
                for (int mi = 0; mi < MT; mi++)
                    mma16(d2[ni][mi], a[mi], (const unsigned*)&bc[ni]);
            #pragma unroll
            for (int ni = 0; ni < 3; ni++) bc[ni] = bn[ni];
        }
        #pragma unroll
        for (int ni = 0; ni < 3; ni++) {
            int pc = 12 * w + 4 * ni + t;
            #pragma unroll
            for (int mi = 0; mi < MT; mi++) {
                int r0 = 16 * mi + g;
                float2 o0 = unpk(s_x[r0 * SXH + pc]);
                float2 o1 = unpk(s_x[(r0 + 8) * SXH + pc]);
                s_x[r0 * SXH + pc]       = pack2h(o0.x - d2[ni][mi][0], o0.y - d2[ni][mi][1]);
                s_x[(r0 + 8) * SXH + pc] = pack2h(o1.x - d2[ni][mi][2], o1.y - d2[ni][mi][3]);
            }
        }
    }
    __syncthreads();

    // ---- GEMM3: pf @ W^T + b -> sigmoid -> blend (12 k16-steps) ----
    {
        float d3[3][MT][4];
        #pragma unroll
        for (int ni = 0; ni < 3; ni++)
            #pragma unroll
            for (int mi = 0; mi < MT; mi++)
                #pragma unroll
                for (int q = 0; q < 4; q++) d3[ni][mi][q] = 0.f;
        int bi = (24 * w + g) * 4 + t;
        uint2 bc[3], bn[3];
        #pragma unroll
        for (int ni = 0; ni < 3; ni++) bc[ni] = __ldg(g_WtH + bi + 32 * ni);
        #pragma unroll 2
        for (int kk = 0; kk < 12; kk++) {
            if (kk + 1 < 12) {
                #pragma unroll
                for (int ni = 0; ni < 3; ni++)
                    bn[ni] = __ldg(g_WtH + (kk + 1) * 768 + bi + 32 * ni);
            }
            unsigned a[MT][4];
            #pragma unroll
            for (int mi = 0; mi < MT; mi++) ldsm4(a[mi], axb[mi] + kk * 32);
            #pragma unroll
            for (int ni = 0; ni < 3; ni++)
                #pragma unroll
                for (int mi = 0; mi < MT; mi++)
                    mma16(d3[ni][mi], a[mi], (const unsigned*)&bc[ni]);
            #pragma unroll
            for (int ni = 0; ni < 3; ni++) bc[ni] = bn[ni];
        }
        #pragma unroll
        for (int ni = 0; ni < 3; ni++) {
            int c = 24 * w + 8 * ni + 2 * t;
            int pc = c >> 1;
            float b0 = __ldg(gate_b + c), b1 = __ldg(gate_b + c + 1);
            #pragma unroll
            for (int mi = 0; mi < MT; mi++) {
                int r0 = 16 * mi + g;
                #pragma unroll
                for (int half = 0; half < 2; half++) {
                    int r = r0 + 8 * half;
                    if (r >= rows) continue;
                    float p0 = d3[ni][mi][2 * half]     + b0;
                    float p1 = d3[ni][mi][2 * half + 1] + b1;
                    float g0 = 1.0f / (1.0f + __expf(-p0));
                    float g1 = 1.0f / (1.0f + __expf(-p1));
                    float2 o2 = *(const float2*)(out + (long)(n0 + r) * FEAT + c);
                    float2 pf = unpk(s_x[r * SXH + pc]);
                    float2 res = make_float2(g0 * o2.x + (1.0f - g0) * pf.x,
                                             g1 * o2.y + (1.0f - g1) * pf.y);
                    *(float2*)(out + (long)(n0 + r) * FEAT + c) = res;
                }
            }
        }
    }
}

extern "C" void kernel_launch(void* const* d_in, const int* in_sizes, int n_in,
                              void* d_out, int out_size) {
    const float* features     = (const float*)d_in[0];   // [N,64]
    const float* rel_emb      = (const float*)d_in[1];   // [R,64]
    const float* proxy        = (const float*)d_in[2];   // [64,192]
    const float* gate_w       = (const float*)d_in[3];   // [192,192]
    const float* gate_b       = (const float*)d_in[4];   // [192]
    const float* attn_kernels = (const float*)d_in[5];   // [2,64]
    const int*   adj          = (const int*)d_in[6];     // [2,E]
    const int*   r_index      = (const int*)d_in[7];     // [2,E]
    const float* r_val        = (const float*)d_in[8];   // [E]
    float* out = (float*)d_out;                          // [N,192]

    const int* src = adj + E_EDGES;
    const int* rid = r_index + E_EDGES;

    setup_kernel<<<TB_TANH + TB_TABS + TB_PREP, 256>>>(
        features, out, rel_emb, attn_kernels, proxy, gate_w);

    __half* fh0; cudaGetSymbolAddress((void**)&fh0, g_fh0);
    __half* fh1; cudaGetSymbolAddress((void**)&fh1, g_fh1);

    int lgrid = (N_NODES * 32 + 255) / 256;
    layer_kernel<<<lgrid, 256>>>(out, fh0, fh1, src, rid, r_val, 0);
    layer_kernel<<<lgrid, 256>>>(out, fh1, (__half*)0, src, rid, r_val, 1);

    size_t smem = (size_t)(NT * SXH + NT * SPH) * sizeof(unsigned) + NT * sizeof(float);
    cudaFuncSetAttribute(final_kernel, cudaFuncAttributeMaxDynamicSharedMemorySize, (int)smem);
    final_kernel<<<(N_NODES + NT - 1) / NT, 256, smem>>>(out, gate_b);
}